// round 17
// baseline (speedup 1.0000x reference)
#include <cuda_runtime.h>
#include <cuda_fp16.h>
#include <cstdint>

// ---------------- problem constants ----------------
#define M_SZ 32768
#define H_SZ 512
#define K_SZ 1024
#define NKC  32              // k32 chunks
#define NSTAGE 4
#define STAGE_BYTES 28672u   // A 4KB + 3 x B 8KB
#define PREF 3

#define SWZ64(x) ((uint32_t)(x) ^ ((((uint32_t)(x)) >> 3) & 0x30))

// A blocks: [m>>6][kc] 4KB  (64 rows x 64B, SW64 pre-swizzled)
// B blocks: [(kc*3+g)*4 + n>>7] 8KB (128 rows x 64B, SW64 pre-swizzled)
__device__ __align__(128) unsigned char g_A[(size_t)M_SZ * 2048];          // 64MB
__device__ __align__(128) unsigned char g_B[(size_t)3 * H_SZ * 2048];      // 3MB

// ---------------- helpers ----------------
__device__ __forceinline__ uint32_t smem_u32(const void* p) {
    uint32_t a;
    asm("{ .reg .u64 t; cvta.to.shared.u64 t, %1; cvt.u32.u64 %0, t; }" : "=r"(a) : "l"(p));
    return a;
}
__device__ __forceinline__ void ldmx4(uint32_t* r, uint32_t a) {
    asm volatile("ldmatrix.sync.aligned.m8n8.x4.shared.b16 {%0,%1,%2,%3}, [%4];"
        : "=r"(r[0]), "=r"(r[1]), "=r"(r[2]), "=r"(r[3]) : "r"(a));
}
__device__ __forceinline__ void mma16816(float* c, const uint32_t* a, uint32_t b0, uint32_t b1) {
    asm volatile("mma.sync.aligned.m16n8k16.row.col.f32.f16.f16.f32 "
        "{%0,%1,%2,%3}, {%4,%5,%6,%7}, {%8,%9}, {%0,%1,%2,%3};"
        : "+f"(c[0]), "+f"(c[1]), "+f"(c[2]), "+f"(c[3])
        : "r"(a[0]), "r"(a[1]), "r"(a[2]), "r"(a[3]), "r"(b0), "r"(b1));
}
__device__ __forceinline__ void mbar_init(uint32_t a, uint32_t cnt) {
    asm volatile("mbarrier.init.shared.b64 [%0], %1;" :: "r"(a), "r"(cnt) : "memory");
}
__device__ __forceinline__ void mbar_expect_tx(uint32_t a, uint32_t tx) {
    asm volatile("mbarrier.arrive.expect_tx.shared.b64 _, [%0], %1;" :: "r"(a), "r"(tx) : "memory");
}
__device__ __forceinline__ void mbar_arrive(uint32_t a) {
    asm volatile("mbarrier.arrive.shared.b64 _, [%0];" :: "r"(a) : "memory");
}
__device__ __forceinline__ void mbar_wait(uint32_t a, uint32_t parity) {
    asm volatile(
        "{\n\t.reg .pred P;\n\t"
        "WL%=:\n\t"
        "mbarrier.try_wait.parity.acquire.cta.shared::cta.b64 P, [%0], %1, 0x989680;\n\t"
        "@P bra WD%=;\n\t"
        "bra WL%=;\n\t"
        "WD%=:\n\t}"
        :: "r"(a), "r"(parity) : "memory");
}
__device__ __forceinline__ void bulk_g2s(uint32_t dst, const void* src, uint32_t bytes, uint32_t mbar) {
    asm volatile(
        "cp.async.bulk.shared::cluster.global.mbarrier::complete_tx::bytes [%0], [%1], %2, [%3];"
        :: "r"(dst), "l"(src), "r"(bytes), "r"(mbar) : "memory");
}

// ---------------- merged prep: A convert + B transpose/convert ----------------
__global__ __launch_bounds__(256)
void prep_ab(const float* __restrict__ x, const float* __restrict__ h,
             const float* __restrict__ Wxi, const float* __restrict__ Whi,
             const float* __restrict__ Wxc, const float* __restrict__ Whc,
             const float* __restrict__ Wxo, const float* __restrict__ Who) {
    if (blockIdx.x < 8192) {
        // ---- prep A: fp32 -> fp16, 64m x k32 blocks, SW64 pre-swizzled ----
        int gid = blockIdx.x * 256 + threadIdx.x;      // 16 elems per thread
        #pragma unroll
        for (int half = 0; half < 2; ++half) {
            int eid = gid * 2 + half;                  // 8-elem unit id
            int m = eid >> 7;
            int k8 = (eid & 127) << 3;
            const float* s = (k8 < 512) ? (x + (size_t)m * 512 + k8)
                                        : (h + (size_t)m * 512 + (k8 - 512));
            float4 v0 = ((const float4*)s)[0];
            float4 v1 = ((const float4*)s)[1];
            __half hh[8];
            hh[0] = __float2half_rn(v0.x); hh[1] = __float2half_rn(v0.y);
            hh[2] = __float2half_rn(v0.z); hh[3] = __float2half_rn(v0.w);
            hh[4] = __float2half_rn(v1.x); hh[5] = __float2half_rn(v1.y);
            hh[6] = __float2half_rn(v1.z); hh[7] = __float2half_rn(v1.w);
            size_t blk = ((size_t)(m >> 6) * NKC + (k8 >> 5)) * 4096;
            uint32_t ob = SWZ64(((m & 63) << 6) + ((k8 & 31) << 1));
            *(uint4*)(g_A + blk + ob) = *(uint4*)hh;
        }
    } else {
        // ---- prep B: transpose + fp16, 8KB blocks, SW64 pre-swizzled ----
        __shared__ float tile[32][33];
        int bid = blockIdx.x - 8192;                   // 0..1535
        int n0 = (bid % 48) * 32;                      // gate-major n
        int k0 = (bid / 48) * 32;
        int g = n0 >> 9;
        int nc0 = n0 & 511;
        const float* Wx = (g == 0) ? Wxi : ((g == 1) ? Wxc : Wxo);
        const float* Wh = (g == 0) ? Whi : ((g == 1) ? Whc : Who);
        int tx = threadIdx.x & 31, ty = threadIdx.x >> 5;   // 32 x 8
        #pragma unroll
        for (int r = ty; r < 32; r += 8) {
            int k = k0 + r;
            const float* W = (k < 512) ? (Wx + (size_t)k * 512) : (Wh + (size_t)(k - 512) * 512);
            tile[r][tx] = W[nc0 + tx];
        }
        __syncthreads();
        #pragma unroll
        for (int r = ty; r < 32; r += 8) {
            float v = tile[tx][r];                 // W[k0+tx][n0+r]
            int n = nc0 + r;
            int k = k0 + tx;
            size_t blk = ((size_t)((k >> 5) * 3 + g) * 4 + (n >> 7)) * 8192;
            uint32_t ob = SWZ64(((n & 127) << 6) + ((k & 31) << 1));
            *(__half*)(g_B + blk + ob) = __float2half_rn(v);
        }
    }
}

// ---------------- fused GEMM + epilogue ----------------
// CTA 64m x 128n x 3 gates; 256 threads = 8 warps (2m x 4n), warp 32x32/gate.
// 2 CTAs/SM. k32 stages, 4-deep, bulk-copy, no syncthreads in mainloop.
// ks-stagger, rotating producer. Inner loop: per ng-phase, batch all 3 gates'
// B-fragment loads back-to-back, then 12 consecutive mma (one LDSM-latency
// exposure per 12 mma instead of three).
__global__ __launch_bounds__(256, 2)
void lstm_gemm(const float* __restrict__ bxi, const float* __restrict__ bxc,
               const float* __restrict__ bxo,
               float* __restrict__ outh, float* __restrict__ outc) {
    extern __shared__ char dsm[];
    const uint32_t sb = (smem_u32(dsm) + 1023) & ~1023u;   // full[4]@0, empty[4]@64
    const uint32_t sd = sb + 1024;                          // stage data

    const int tid  = threadIdx.x;
    const int lane = tid & 31;
    const int wid  = tid >> 5;
    const int wm   = wid >> 2;       // 0..1 -> m offset 32*wm
    const int wn   = wid & 3;        // 0..3 -> n offset 32*wn
    const int ksx  = wid & 1;        // ks processing order stagger
    const int m0   = blockIdx.y << 6;
    const int n0   = blockIdx.x << 7;
    const int mb   = blockIdx.y;
    const int nb   = blockIdx.x;

    if (tid == 0) {
        #pragma unroll
        for (int s = 0; s < NSTAGE; ++s) {
            mbar_init(sb + 8 * s, 1);        // full: tx-based
            mbar_init(sb + 64 + 8 * s, 8);   // empty: 8 warp arrivals
        }
        asm volatile("fence.proxy.async.shared::cta;" ::: "memory");
    }
    __syncthreads();

    auto issue_chunk = [&](int c) {
        const int s = c % NSTAGE;
        const uint32_t mbar = sb + 8 * s;
        const uint32_t dst = sd + (uint32_t)s * STAGE_BYTES;
        mbar_expect_tx(mbar, STAGE_BYTES);
        bulk_g2s(dst, g_A + ((size_t)mb * NKC + c) * 4096, 4096u, mbar);
        #pragma unroll
        for (int g = 0; g < 3; ++g)
            bulk_g2s(dst + 4096u + 8192u * g,
                     g_B + ((size_t)((c * 3 + g) * 4) + nb) * 8192, 8192u, mbar);
    };

    if (tid == 0) {
        issue_chunk(0);
        issue_chunk(1);
        issue_chunk(2);
    }

    // ldmatrix bases (SW64, 64B rows); per-ks XOR 32
    uint32_t a_base[2];
    #pragma unroll
    for (int mt = 0; mt < 2; ++mt) {
        int row = (wm << 5) + (mt << 4) + (lane & 15);
        int ro  = row * 64 + ((lane >> 4) << 4);
        a_base[mt] = SWZ64(ro);
    }
    uint32_t b_base[2];
    #pragma unroll
    for (int ng = 0; ng < 2; ++ng) {
        int rr = (wn << 5) + (ng << 4) + (lane & 7) + (((lane >> 4) & 1) << 3);
        int ro = rr * 64 + (((lane >> 3) & 1) << 4);
        b_base[ng] = SWZ64(ro);
    }

    float c[3][2][4][4];   // gate, mt, nt, e -> 96 regs
    #pragma unroll
    for (int g = 0; g < 3; ++g)
        #pragma unroll
        for (int mt = 0; mt < 2; ++mt)
            #pragma unroll
            for (int nt = 0; nt < 4; ++nt)
                #pragma unroll
                for (int e = 0; e < 4; ++e) c[g][mt][nt][e] = 0.0f;

    for (int ch = 0; ch < NKC; ++ch) {
        const int s = ch % NSTAGE;
        mbar_wait(sb + 8 * s, (ch / NSTAGE) & 1);

        const uint32_t sA = sd + (uint32_t)s * STAGE_BYTES;
        const uint32_t sB = sA + 4096u;

        #pragma unroll
        for (int kss = 0; kss < 2; ++kss) {
            const int ks = kss ^ ksx;                 // stagger across warps
            const uint32_t kx = (uint32_t)(ks << 5);
            uint32_t af[2][4];
            ldmx4(af[0], sA + (a_base[0] ^ kx));
            ldmx4(af[1], sA + (a_base[1] ^ kx));
            #pragma unroll
            for (int ng = 0; ng < 2; ++ng) {
                // batch all 3 gates' B loads: latencies overlap
                uint32_t bh[3][4];
                ldmx4(bh[0], sB + (uint32_t)(0 << 13) + (b_base[ng] ^ kx));
                ldmx4(bh[1], sB + (uint32_t)(1 << 13) + (b_base[ng] ^ kx));
                ldmx4(bh[2], sB + (uint32_t)(2 << 13) + (b_base[ng] ^ kx));
                #pragma unroll
                for (int g = 0; g < 3; ++g) {
                    #pragma unroll
                    for (int mt = 0; mt < 2; ++mt) {
                        mma16816(c[g][mt][2*ng+0], af[mt], bh[g][0], bh[g][1]);
                        mma16816(c[g][mt][2*ng+1], af[mt], bh[g][2], bh[g][3]);
                    }
                }
            }
        }

        if (lane == 0) mbar_arrive(sb + 64 + 8 * s);

        // producer rotation: chunk cn issued by warp cn%8 (lane 0)
        const int cn = ch + PREF;
        if (cn < NKC && wid == (cn & 7) && lane == 0) {
            if (cn >= NSTAGE)
                mbar_wait(sb + 64 + 8 * (cn % NSTAGE), ((cn / NSTAGE) - 1) & 1);
            issue_chunk(cn);
        }
    }

    // ---- fused epilogue ----
    const int ncb = n0 + (wn << 5) + ((lane & 3) << 1);
    float2 bi2[4], bc2[4], bo2[4];
    #pragma unroll
    for (int nt = 0; nt < 4; ++nt) {
        bi2[nt] = *(const float2*)(bxi + ncb + nt * 8);
        bc2[nt] = *(const float2*)(bxc + ncb + nt * 8);
        bo2[nt] = *(const float2*)(bxo + ncb + nt * 8);
    }

    #pragma unroll
    for (int mt = 0; mt < 2; ++mt) {
        #pragma unroll
        for (int half = 0; half < 2; ++half) {
            int m = m0 + (wm << 5) + (mt << 4) + (lane >> 2) + half * 8;
            size_t ob = (size_t)m * 512;
            #pragma unroll
            for (int nt = 0; nt < 4; ++nt) {
                float hv[2], cv[2];
                #pragma unroll
                for (int e = 0; e < 2; ++e) {
                    int idx = half * 2 + e;
                    float ip = c[0][mt][nt][idx] + (e ? bi2[nt].y : bi2[nt].x);
                    float cp = c[1][mt][nt][idx] + (e ? bc2[nt].y : bc2[nt].x);
                    float op = c[2][mt][nt][idx] + (e ? bo2[nt].y : bo2[nt].x);
                    float ig = 1.0f / (1.0f + __expf(-ip));
                    float og = 1.0f / (1.0f + __expf(-op));
                    float tc = 1.0f - 2.0f / (__expf(2.0f * cp) + 1.0f);
                    float cn2 = ig * tc;
                    float tn = 1.0f - 2.0f / (__expf(2.0f * cn2) + 1.0f);
                    cv[e] = cn2;
                    hv[e] = og * tn;
                }
                *(float2*)(outh + ob + ncb + nt * 8) = *(float2*)hv;
                *(float2*)(outc + ob + ncb + nt * 8) = *(float2*)cv;
            }
        }
    }
}

// ---------------- launcher ----------------
extern "C" void kernel_launch(void* const* d_in, const int* in_sizes, int n_in,
                              void* d_out, int out_size) {
    // 0:x 1:h 2:c_prev 3:Wxi 4:bxi 5:Whi 6:Wxf 7:bxf 8:Whf 9:Wxc 10:bxc 11:Whc 12:Wxo 13:bxo 14:Who
    const float* x   = (const float*)d_in[0];
    const float* h   = (const float*)d_in[1];
    const float* Wxi = (const float*)d_in[3];
    const float* bxi = (const float*)d_in[4];
    const float* Whi = (const float*)d_in[5];
    const float* Wxc = (const float*)d_in[9];
    const float* bxc = (const float*)d_in[10];
    const float* Whc = (const float*)d_in[11];
    const float* Wxo = (const float*)d_in[12];
    const float* bxo = (const float*)d_in[13];
    const float* Who = (const float*)d_in[14];

    float* outh = (float*)d_out;
    float* outc = outh + (size_t)M_SZ * H_SZ;

    const int smem = 1024 + NSTAGE * (int)STAGE_BYTES;   // 115712 -> 2 CTAs/SM
    cudaFuncSetAttribute(lstm_gemm, cudaFuncAttributeMaxDynamicSharedMemorySize, smem);

    prep_ab<<<8192 + 1536, 256>>>(x, h, Wxi, Whi, Wxc, Whc, Wxo, Who);
    lstm_gemm<<<dim3(4, 512), 256, smem>>>(bxi, bxc, bxo, outh, outc);
}